// round 11
// baseline (speedup 1.0000x reference)
#include <cuda_runtime.h>
#include <math.h>

#define NROWS 1048576
#define D     128
#define G     4096
#define HID   50
#define GDIM  201
#define TAILW 33
#define OUTW  (GDIM + TAILW)   // 234

#define SCONS       8                        // smem-consumer warps
#define DCONS       7                        // direct-LDG warps
#define NWARPS      (SCONS + DCONS + 1)      // +1 producer = 16
#define THREADS     (NWARPS * 32)            // 512
#define RPS         32                       // rows per stage
#define STAGES      4
#define ROW_BYTES   512                      // 128 floats
#define STAGE_BYTES (RPS * ROW_BYTES)        // 16 KB
#define RING_BYTES  (STAGES * STAGE_BYTES)   // 64 KB dynamic smem

// ---------------- persistent scratch (no allocations allowed) ----------------
__device__ int g_start[G + 1];

// ---------------- kernel 0: group boundaries via parallel lower_bound --------
__global__ void bounds_kernel(const int* __restrict__ batch) {
    int g = blockIdx.x * blockDim.x + threadIdx.x;
    if (g > G) return;
    int lo = 0, hi = NROWS;
    while (lo < hi) {
        int mid = (lo + hi) >> 1;
        if (__ldg(&batch[mid]) < g) lo = mid + 1; else hi = mid;
    }
    g_start[g] = lo;
}

// ---------------- mbarrier helpers ----------------
__device__ __forceinline__ unsigned smem_u32(const void* p) {
    return (unsigned)__cvta_generic_to_shared(p);
}
__device__ __forceinline__ void mbar_init(unsigned mbar, unsigned count) {
    asm volatile("mbarrier.init.shared.b64 [%0], %1;" :: "r"(mbar), "r"(count) : "memory");
}
__device__ __forceinline__ void mbar_expect_tx(unsigned mbar, unsigned bytes) {
    asm volatile("mbarrier.arrive.expect_tx.shared.b64 _, [%0], %1;"
                 :: "r"(mbar), "r"(bytes) : "memory");
}
__device__ __forceinline__ void mbar_arrive(unsigned mbar) {
    asm volatile("mbarrier.arrive.release.cta.shared::cta.b64 _, [%0];"
                 :: "r"(mbar) : "memory");
}
__device__ __forceinline__ void mbar_wait(unsigned mbar, unsigned parity) {
    asm volatile(
        "{\n\t"
        ".reg .pred P;\n\t"
        "WAIT_%=:\n\t"
        "mbarrier.try_wait.parity.acquire.cta.shared::cta.b64 P, [%0], %1, 0x989680;\n\t"
        "@P bra.uni DONE_%=;\n\t"
        "bra.uni WAIT_%=;\n\t"
        "DONE_%=:\n\t"
        "}"
        :: "r"(mbar), "r"(parity) : "memory");
}
__device__ __forceinline__ void bulk_copy_g2s(unsigned dst_smem, const void* src,
                                              unsigned bytes, unsigned mbar) {
    asm volatile(
        "cp.async.bulk.shared::cta.global.mbarrier::complete_tx::bytes [%0], [%1], %2, [%3];"
        :: "r"(dst_smem), "l"(src), "r"(bytes), "r"(mbar) : "memory");
}

// ---------------- accumulator ----------------
struct Acc {
    float4 s, s2, mx, mn;
    __device__ __forceinline__ void init() {
        s  = make_float4(0.f, 0.f, 0.f, 0.f);
        s2 = make_float4(0.f, 0.f, 0.f, 0.f);
        const float NEGI = __int_as_float(0xff800000);
        const float POSI = __int_as_float(0x7f800000);
        mx = make_float4(NEGI, NEGI, NEGI, NEGI);
        mn = make_float4(POSI, POSI, POSI, POSI);
    }
    __device__ __forceinline__ void add(const float4& v) {
        s.x += v.x; s.y += v.y; s.z += v.z; s.w += v.w;
        s2.x = fmaf(v.x, v.x, s2.x);
        s2.y = fmaf(v.y, v.y, s2.y);
        s2.z = fmaf(v.z, v.z, s2.z);
        s2.w = fmaf(v.w, v.w, s2.w);
        mx.x = fmaxf(mx.x, v.x); mx.y = fmaxf(mx.y, v.y);
        mx.z = fmaxf(mx.z, v.z); mx.w = fmaxf(mx.w, v.w);
        mn.x = fminf(mn.x, v.x); mn.y = fminf(mn.y, v.y);
        mn.z = fminf(mn.z, v.z); mn.w = fminf(mn.w, v.w);
    }
};

// ---------------- fused hybrid kernel ----------------
extern __shared__ char ring[];   // 64 KB; reused as reduction scratch after streaming

__global__ void __launch_bounds__(THREADS)
fused_kernel(const float* __restrict__ x, const float* __restrict__ u,
             const float* __restrict__ W1, const float* __restrict__ b1,
             const float* __restrict__ ln_g, const float* __restrict__ ln_b,
             const float* __restrict__ W2, const float* __restrict__ b2,
             float* __restrict__ out) {
    __shared__ __align__(8) unsigned long long full_b [STAGES];
    __shared__ __align__(8) unsigned long long empty_b[STAGES];
    __shared__ float aggr[4 * D];
    __shared__ float part[HID][4];
    __shared__ float hn[HID];
    __shared__ float mu_s, rstd_s;

    const int gid  = blockIdx.x;
    const int t    = threadIdx.x;
    const int w    = t >> 5;
    const int lane = t & 31;

    const int s    = g_start[gid];
    const int rows = g_start[gid + 1] - s;

    // split: front half via TMA ring, back half via direct LDG
    const int smem_rows = rows >> 1;
    const int dir_rows  = rows - smem_rows;
    const int nst = (smem_rows + RPS - 1) / RPS;
    const char* xbase = (const char*)x + (size_t)s * ROW_BYTES;

    if (t == 0) {
#pragma unroll
        for (int k = 0; k < STAGES; ++k) {
            mbar_init(smem_u32(&full_b[k]),  1);
            mbar_init(smem_u32(&empty_b[k]), SCONS);
        }
    }
    __syncthreads();

    Acc acc;
    acc.init();

    if (w == NWARPS - 1) {
        // -------- producer warp --------
        if (lane == 0) {
            for (int k = 0; k < nst; ++k) {
                int slot = k % STAGES;
                int r    = k / STAGES;
                if (k >= STAGES)
                    mbar_wait(smem_u32(&empty_b[slot]), (r - 1) & 1);
                unsigned bytes = (unsigned)(min(smem_rows - k * RPS, RPS) * ROW_BYTES);
                unsigned mb = smem_u32(&full_b[slot]);
                mbar_expect_tx(mb, bytes);
                bulk_copy_g2s(smem_u32(ring + slot * STAGE_BYTES),
                              xbase + (size_t)k * STAGE_BYTES, bytes, mb);
            }
        }
    } else if (w < SCONS) {
        // -------- smem consumer warps --------
        for (int k = 0; k < nst; ++k) {
            int slot = k % STAGES;
            mbar_wait(smem_u32(&full_b[slot]), (k / STAGES) & 1);

            const char* sp  = ring + slot * STAGE_BYTES;
            const int rbase = k * RPS;
#pragma unroll
            for (int j = 0; j < RPS / SCONS; ++j) {   // 4 rows/warp/stage
                int rr = w * (RPS / SCONS) + j;
                if (rbase + rr < smem_rows)
                    acc.add(*(const float4*)(sp + rr * ROW_BYTES + lane * 16));
            }
            if (lane == 0) mbar_arrive(smem_u32(&empty_b[slot]));
        }
    } else {
        // -------- direct LDG warps --------
        const int wd    = w - SCONS;                      // 0..DCONS-1
        const int chunk = (dir_rows + DCONS - 1) / DCONS;
        const int rs    = min(wd * chunk, dir_rows);
        const int re    = min(rs + chunk, dir_rows);
        const float4* __restrict__ X4 = (const float4*)x;
        const size_t base = (size_t)(s + smem_rows);

        int r = rs;
        for (; r + 4 <= re; r += 4) {
            // 4 independent LDG.128 in flight before consumption
            float4 v0 = X4[(base + r + 0) * 32 + lane];
            float4 v1 = X4[(base + r + 1) * 32 + lane];
            float4 v2 = X4[(base + r + 2) * 32 + lane];
            float4 v3 = X4[(base + r + 3) * 32 + lane];
            acc.add(v0); acc.add(v1); acc.add(v2); acc.add(v3);
        }
        for (; r < re; ++r)
            acc.add(X4[(base + r) * 32 + lane]);
    }
    __syncthreads();   // streaming + direct both complete; ring reusable

    // ---- cross-warp reduction: 15 accumulating warps -> ring scratch ----
    const int AW = SCONS + DCONS;            // 15
    float* red = (float*)ring;               // [arr][warp][col]  4*15*128*4B = 30 KB
    if (w < AW) {
        *(float4*)&red[(0 * AW + w) * D + lane * 4] = acc.s;
        *(float4*)&red[(1 * AW + w) * D + lane * 4] = acc.s2;
        *(float4*)&red[(2 * AW + w) * D + lane * 4] = acc.mx;
        *(float4*)&red[(3 * AW + w) * D + lane * 4] = acc.mn;
    }
    __syncthreads();

    if (t < D) {
        const float NEGI = __int_as_float(0xff800000);
        const float POSI = __int_as_float(0x7f800000);
        float sm = 0.f, sm2 = 0.f, mx = NEGI, mn = POSI;
#pragma unroll
        for (int ww = 0; ww < AW; ++ww) {
            sm  += red[(0 * AW + ww) * D + t];
            sm2 += red[(1 * AW + ww) * D + t];
            mx   = fmaxf(mx, red[(2 * AW + ww) * D + t]);
            mn   = fminf(mn, red[(3 * AW + ww) * D + t]);
        }
        float c    = fmaxf((float)rows, 1.0f);
        float mean = sm / c;
        float var  = sm2 / c - mean * mean;
        aggr[t]         = mean;
        aggr[D + t]     = sqrtf(fmaxf(var, 0.0f) + 1e-5f);
        aggr[2 * D + t] = mx;
        aggr[3 * D + t] = mn;
    }
    __syncthreads();

    // ---- h = aggr(512) @ W1(512,50): 4 slice-partials per output ----
    if (t < 4 * HID) {
        int j  = t >> 2;
        int sl = t & 3;
        const float* __restrict__ wp = W1 + (sl * D) * HID + j;
        const float* __restrict__ a  = aggr + sl * D;
        float a2 = 0.0f;
#pragma unroll 8
        for (int k = 0; k < D; ++k) a2 = fmaf(a[k], wp[k * HID], a2);
        part[j][sl] = a2;
    }
    __syncthreads();

    if (t < HID) {
        float hv = part[t][0] + part[t][1] + part[t][2] + part[t][3] + b1[t];
        const float SC = 1.0507009873554804934193349852946f;
        const float AL = 1.6732632423543772848170429916717f;
        hv = (hv > 0.0f) ? SC * hv : SC * AL * expm1f(hv);
        hn[t] = hv;
    }
    __syncthreads();

    if (t == 0) {
        float m = 0.0f;
#pragma unroll
        for (int k = 0; k < HID; ++k) m += hn[k];
        m /= (float)HID;
        float v = 0.0f;
#pragma unroll
        for (int k = 0; k < HID; ++k) { float d = hn[k] - m; v = fmaf(d, d, v); }
        v /= (float)HID;
        mu_s   = m;
        rstd_s = rsqrtf(v + 1e-5f);
    }
    __syncthreads();

    if (t < HID) hn[t] = (hn[t] - mu_s) * rstd_s * ln_g[t] + ln_b[t];
    __syncthreads();

    if (t < GDIM) {
        float a3 = b2[t];
#pragma unroll
        for (int k = 0; k < HID; ++k) a3 = fmaf(hn[k], W2[k * GDIM + t], a3);
        out[gid * OUTW + t] = a3;
    } else if (t < OUTW) {
        out[gid * OUTW + t] = u[gid * 64 + 31 + (t - GDIM)];
    }
}

// ---------------- launch ----------------
extern "C" void kernel_launch(void* const* d_in, const int* in_sizes, int n_in,
                              void* d_out, int out_size) {
    const float* x     = (const float*)d_in[0];
    // d_in[1] edge_index, d_in[2] edge_attr: unused by the reference
    const float* u     = (const float*)d_in[3];
    const int*   batch = (const int*)d_in[4];
    const float* W1    = (const float*)d_in[5];
    const float* b1    = (const float*)d_in[6];
    const float* ln_g  = (const float*)d_in[7];
    const float* ln_b  = (const float*)d_in[8];
    const float* W2    = (const float*)d_in[9];
    const float* b2    = (const float*)d_in[10];
    float* out = (float*)d_out;

    cudaFuncSetAttribute(fused_kernel,
                         cudaFuncAttributeMaxDynamicSharedMemorySize, RING_BYTES);

    bounds_kernel<<<(G + 1 + 255) / 256, 256>>>(batch);
    fused_kernel<<<G, THREADS, RING_BYTES>>>(x, u, W1, b1, ln_g, ln_b, W2, b2, out);
}